// round 15
// baseline (speedup 1.0000x reference)
#include <cuda_runtime.h>
#include <cstdint>

// Fixed problem shape
#define HH 128
#define WW 240
#define NG 40
#define CPG 8
#define DD 48
#define PADL 48
#define NPOS (WW + PADL)   // 288 positions per smem row
#define ROWA 292           // stride ≡ 4 (mod 8): kh halves hit disjoint bank sets
#define TPB 256

#define SMEM_UNIT (2 * CPG * ROWA)     // floats per unit buffer (16 rows)

#define GWC_BLOCKS (NG * (HH / 4))     // 1280 (each block: 4 h rows = 2 units)
#define CAT_BLOCKS (24 * DD)           // 1152
#define MIX_LIMIT (CAT_BLOCKS * 2)     // 2304: alternate gwc/cat
#define TOTAL_BLOCKS (GWC_BLOCKS + CAT_BLOCKS)  // 2432

__device__ __forceinline__ void stcs4(float* p, float4 v) { __stcs((float4*)p, v); }
__device__ __forceinline__ void stcs2(float* p, float2 v) { __stcs((float2*)p, v); }

__device__ __forceinline__ uint32_t smem_u32(const void* p) {
    return (uint32_t)__cvta_generic_to_shared(p);
}
__device__ __forceinline__ void cpasync16(uint32_t dst, const void* src) {
    asm volatile("cp.async.cg.shared.global [%0], [%1], 16;" :: "r"(dst), "l"(src));
}
#define CP_COMMIT() asm volatile("cp.async.commit_group;")
#define CP_WAIT(N)  asm volatile("cp.async.wait_group %0;" :: "n"(N))

// 6 resident blocks/SM: 6 x 37376 B = 224 KB smem (fits 228 KB carveout),
// 1536 thr x 64 regs = 98K regs (fits 256K RF). Occupancy was the artificial cap.
__global__ __launch_bounds__(TPB, 6)
void fused_kernel(const float* __restrict__ ref, const float* __restrict__ tgt,
                  const float* __restrict__ refc, const float* __restrict__ tgtc,
                  float* __restrict__ out) {
    __shared__ __align__(16) float s[2 * SMEM_UNIT];   // 37376 B (2 unit buffers)

    const int bid = blockIdx.x;
    const int tid = threadIdx.x;

    // ---- interleave: first 2304 blocks alternate gwc/cat, tail is gwc ----
    bool is_cat;
    int wid_;
    if (bid < MIX_LIMIT) {
        is_cat = (bid & 1);
        wid_ = bid >> 1;
    } else {
        is_cat = false;
        wid_ = CAT_BLOCKS + (bid - MIX_LIMIT);   // 1152..1279
    }

    if (!is_cat) {
        // ===== gwc block: group g, h rows hb..hb+3, two pipelined units =====
        const int g  = wid_ % NG;
        const int hb = (wid_ / NG) * 4;

        // pad zeros for both buffers (positions < PADL): 2 x 16 rows x 12 quads
        for (int i = tid; i < 2 * 16 * 12; i += TPB) {
            const int b = i / (16 * 12), r2 = (i / 12) & 15, j = i % 12;
            *(float4*)(s + b * SMEM_UNIT + r2 * ROWA + j * 4) =
                make_float4(0.f, 0.f, 0.f, 0.f);
        }
        // issue BOTH units' tile loads up front; unit 1 streams in during unit 0 compute
#pragma unroll
        for (int u = 0; u < 2; ++u) {
            const int h0 = hb + u * 2;
            float* dbase = s + u * SMEM_UNIT;
            for (int i = tid; i < 16 * 60; i += TPB) {
                const int r2 = i / 60, j = i - r2 * 60;
                const int c = r2 & 7, hr = r2 >> 3;
                const float* src = tgt + (((size_t)(g * CPG + c)) * HH + h0 + hr) * WW + j * 4;
                cpasync16(smem_u32(dbase + r2 * ROWA + PADL + j * 4), src);
            }
            CP_COMMIT();
        }

        // per-thread role (same for both units)
        const int sub = tid & 127;
        const int hr  = tid >> 7;          // which h row of the unit (warp-uniform)
        const int kh  = sub & 1;           // 0 -> channels 0..3, 1 -> channels 4..7
        int q = sub >> 1;                  // w-quad id 0..63
        const bool active = (q < 60);
        if (q > 59) q = 59;                // keep warps converged for shfl
        const int w4 = q * 4;

        auto compute = [&](int u) {
            const int h = hb + u * 2 + hr;

            // ref: 4 channels x 4 w, x1/8 folded (16 regs)
            float r[4][4];
#pragma unroll
            for (int k = 0; k < 4; ++k) {
                float4 v = *(const float4*)(ref + (((size_t)(g * CPG + kh * 4 + k)) * HH + h) * WW + w4);
                r[k][0] = v.x * 0.125f; r[k][1] = v.y * 0.125f;
                r[k][2] = v.z * 0.125f; r[k][3] = v.w * 0.125f;
            }

            const float* sbase = s + u * SMEM_UNIT + (hr * 8 + kh * 4) * ROWA;

            float4 A[4], B[4];             // rolling quads (32 regs)
#pragma unroll
            for (int k = 0; k < 4; ++k)
                B[k] = *(const float4*)(sbase + k * ROWA + PADL + w4);

            int pb = PADL + w4 - 4;        // quad-aligned, >= 0 for all groups
            float* op = out + ((size_t)g * DD * HH + h) * WW + w4 + 2 * kh;

            // one disparity sub-step: F = [LO|HI] flattened, out j uses F[4 + j - T]
#define GWC_STEP(LO, HI, T)                                                     \
            {                                                                   \
                float a0 = 0.f, a1 = 0.f, a2 = 0.f, a3 = 0.f;                   \
                _Pragma("unroll")                                               \
                for (int k = 0; k < 4; ++k) {                                   \
                    const float F[8] = { LO[k].x, LO[k].y, LO[k].z, LO[k].w,    \
                                         HI[k].x, HI[k].y, HI[k].z, HI[k].w };  \
                    a0 += r[k][0] * F[4 + 0 - (T)];                             \
                    a1 += r[k][1] * F[4 + 1 - (T)];                             \
                    a2 += r[k][2] * F[4 + 2 - (T)];                             \
                    a3 += r[k][3] * F[4 + 3 - (T)];                             \
                }                                                               \
                float v0 = kh ? a0 : a2;                                        \
                float v1 = kh ? a1 : a3;                                        \
                float u0 = __shfl_xor_sync(0xffffffffu, v0, 1);                 \
                float u1 = __shfl_xor_sync(0xffffffffu, v1, 1);                 \
                if (active) {                                                   \
                    float2 o;                                                   \
                    if (kh == 0) { o.x = a0 + u0; o.y = a1 + u1; }              \
                    else         { o.x = a2 + u0; o.y = a3 + u1; }              \
                    stcs2(op, o);                                               \
                }                                                               \
                op += HH * WW;                                                  \
            }

#pragma unroll
            for (int dp = 0; dp < DD / 8; ++dp) {
                // group A: lo = A (newly loaded), hi = B
#pragma unroll
                for (int k = 0; k < 4; ++k) A[k] = *(const float4*)(sbase + k * ROWA + pb);
                GWC_STEP(A, B, 0) GWC_STEP(A, B, 1) GWC_STEP(A, B, 2) GWC_STEP(A, B, 3)
                pb -= 4;
                // group B: lo = B (newly loaded), hi = A
#pragma unroll
                for (int k = 0; k < 4; ++k) B[k] = *(const float4*)(sbase + k * ROWA + pb);
                GWC_STEP(B, A, 0) GWC_STEP(B, A, 1) GWC_STEP(B, A, 2) GWC_STEP(B, A, 3)
                pb -= 4;
            }
#undef GWC_STEP
        };

        CP_WAIT(1);            // unit 0 tile resident (groups retire in order)
        __syncthreads();       // pad zeros + unit 0 visible to all
        compute(0);
        CP_WAIT(0);            // unit 1 tile resident (streamed during compute(0))
        __syncthreads();
        compute(1);
    } else {
        // ===== concat block: one (c, d) plane; 240 threads = 60 wq x 4 h-quarters =====
        const int d = wid_ % DD;
        const int c = wid_ / DD;
        if (tid >= 240) return;
        const int wq = tid % 60;
        const int qt = tid / 60;           // h quarter (32 rows)
        const int wb = wq * 4;
        const int h0 = qt * 32;

        float* ob = out + ((((size_t)(NG + c) * DD + d) * HH) + h0) * WW + wb;

        if (c < 12) {
            const bool m0 = (wb + 0 >= d), m1 = (wb + 1 >= d),
                       m2 = (wb + 2 >= d), m3 = (wb + 3 >= d);
            const float* ib = refc + (((size_t)c * HH) + h0) * WW + wb;
#pragma unroll 4
            for (int h = 0; h < 32; ++h) {
                float4 x = *(const float4*)(ib + h * WW);
                float4 v;
                v.x = m0 ? x.x : 0.f;
                v.y = m1 ? x.y : 0.f;
                v.z = m2 ? x.z : 0.f;
                v.w = m3 ? x.w : 0.f;
                stcs4(ob + h * WW, v);
            }
        } else {
            // right-shifted tgt plane via aligned quad pair + uniform select
            const float* base = tgtc + (((size_t)(c - 12) * HH) + h0) * WW;
            const int sh = d & 3;
            if (sh == 0) {
                const int lo = wb - d;                 // quad aligned
                if (lo >= 0) {
                    const float* ib = base + lo;
#pragma unroll 4
                    for (int h = 0; h < 32; ++h)
                        stcs4(ob + h * WW, *(const float4*)(ib + h * WW));
                } else {
                    float4 z = make_float4(0.f, 0.f, 0.f, 0.f);
#pragma unroll 4
                    for (int h = 0; h < 32; ++h)
                        stcs4(ob + h * WW, z);
                }
            } else {
                const int off = 4 - sh;                // 1..3
                const int lo = wb - d - off;           // quad aligned
                const int hi4 = lo + 4;                // <= 236 when >= 0: in bounds
                const bool ldlo = (lo >= 0), ldhi = (hi4 >= 0);
                const float4 z = make_float4(0.f, 0.f, 0.f, 0.f);
#pragma unroll 4
                for (int h = 0; h < 32; ++h) {
                    float4 L = ldlo ? *(const float4*)(base + h * WW + lo)  : z;
                    float4 H = ldhi ? *(const float4*)(base + h * WW + hi4) : z;
                    float4 v;
                    if (off == 1)      { v.x = L.y; v.y = L.z; v.z = L.w; v.w = H.x; }
                    else if (off == 2) { v.x = L.z; v.y = L.w; v.z = H.x; v.w = H.y; }
                    else               { v.x = L.w; v.y = H.x; v.z = H.y; v.w = H.z; }
                    stcs4(ob + h * WW, v);
                }
            }
        }
    }
}

extern "C" void kernel_launch(void* const* d_in, const int* in_sizes, int n_in,
                              void* d_out, int out_size) {
    const float* ref_gwc    = (const float*)d_in[0];
    const float* tgt_gwc    = (const float*)d_in[1];
    const float* ref_concat = (const float*)d_in[2];
    const float* tgt_concat = (const float*)d_in[3];
    float* out = (float*)d_out;

    fused_kernel<<<TOTAL_BLOCKS, TPB>>>(ref_gwc, tgt_gwc, ref_concat, tgt_concat, out);
}

// round 16
// speedup vs baseline: 1.7157x; 1.7157x over previous
#include <cuda_runtime.h>
#include <cstdint>

// Fixed problem shape
#define HH 128
#define WW 240
#define NG 40
#define CPG 8
#define DD 48
#define PADL 48
#define NPOS (WW + PADL)   // 288 positions per smem row
#define ROWA 292           // stride ≡ 4 (mod 8): kh halves hit disjoint bank sets
#define TPB 256

#define SMEM_UNIT (2 * CPG * ROWA)     // floats per unit buffer (16 rows)

#define GWC_BLOCKS (NG * (HH / 4))     // 1280 (each block: 4 h rows = 2 units)
#define CAT_BLOCKS (24 * DD)           // 1152
#define EXTRA_GWC (GWC_BLOCKS - CAT_BLOCKS)   // 128 unpaired gwc blocks, launched FIRST
#define TOTAL_BLOCKS (GWC_BLOCKS + CAT_BLOCKS)  // 2432

__device__ __forceinline__ void stwt4(float* p, float4 v) { __stwt((float4*)p, v); }
__device__ __forceinline__ void stwt2(float* p, float2 v) { __stwt((float2*)p, v); }

__device__ __forceinline__ uint32_t smem_u32(const void* p) {
    return (uint32_t)__cvta_generic_to_shared(p);
}
__device__ __forceinline__ void cpasync16(uint32_t dst, const void* src) {
    asm volatile("cp.async.cg.shared.global [%0], [%1], 16;" :: "r"(dst), "l"(src));
}
#define CP_COMMIT() asm volatile("cp.async.commit_group;")
#define CP_WAIT(N)  asm volatile("cp.async.wait_group %0;" :: "n"(N))

// RF cap: 64K regs/SM -> 1024 threads at 64 regs = 4 blocks of 256. (6 forced a spill in R15.)
__global__ __launch_bounds__(TPB, 4)
void fused_kernel(const float* __restrict__ ref, const float* __restrict__ tgt,
                  const float* __restrict__ refc, const float* __restrict__ tgtc,
                  float* __restrict__ out) {
    __shared__ __align__(16) float s[2 * SMEM_UNIT];   // 37376 B (2 unit buffers)

    const int bid = blockIdx.x;
    const int tid = threadIdx.x;

    // ---- schedule: 128 pure-gwc blocks first (longest pole), then alternate gwc/cat ----
    bool is_cat;
    int wid_;
    if (bid < EXTRA_GWC) {
        is_cat = false;
        wid_ = CAT_BLOCKS + bid;            // 1152..1279
    } else {
        const int b = bid - EXTRA_GWC;      // 0..2303
        is_cat = (b & 1);
        wid_ = b >> 1;                      // 0..1151
    }

    if (!is_cat) {
        // ===== gwc block: group g, h rows hb..hb+3, two pipelined units =====
        const int g  = wid_ % NG;
        const int hb = (wid_ / NG) * 4;

        // pad zeros for both buffers (positions < PADL): 2 x 16 rows x 12 quads
        for (int i = tid; i < 2 * 16 * 12; i += TPB) {
            const int b = i / (16 * 12), r2 = (i / 12) & 15, j = i % 12;
            *(float4*)(s + b * SMEM_UNIT + r2 * ROWA + j * 4) =
                make_float4(0.f, 0.f, 0.f, 0.f);
        }
        // issue BOTH units' tile loads up front; unit 1 streams in during unit 0 compute
#pragma unroll
        for (int u = 0; u < 2; ++u) {
            const int h0 = hb + u * 2;
            float* dbase = s + u * SMEM_UNIT;
            for (int i = tid; i < 16 * 60; i += TPB) {
                const int r2 = i / 60, j = i - r2 * 60;
                const int c = r2 & 7, hr = r2 >> 3;
                const float* src = tgt + (((size_t)(g * CPG + c)) * HH + h0 + hr) * WW + j * 4;
                cpasync16(smem_u32(dbase + r2 * ROWA + PADL + j * 4), src);
            }
            CP_COMMIT();
        }

        // per-thread role (same for both units)
        const int sub = tid & 127;
        const int hr  = tid >> 7;          // which h row of the unit (warp-uniform)
        const int kh  = sub & 1;           // 0 -> channels 0..3, 1 -> channels 4..7
        int q = sub >> 1;                  // w-quad id 0..63
        const bool active = (q < 60);
        if (q > 59) q = 59;                // keep warps converged for shfl
        const int w4 = q * 4;

        auto compute = [&](int u) {
            const int h = hb + u * 2 + hr;

            // ref: 4 channels x 4 w, x1/8 folded (16 regs)
            float r[4][4];
#pragma unroll
            for (int k = 0; k < 4; ++k) {
                float4 v = *(const float4*)(ref + (((size_t)(g * CPG + kh * 4 + k)) * HH + h) * WW + w4);
                r[k][0] = v.x * 0.125f; r[k][1] = v.y * 0.125f;
                r[k][2] = v.z * 0.125f; r[k][3] = v.w * 0.125f;
            }

            const float* sbase = s + u * SMEM_UNIT + (hr * 8 + kh * 4) * ROWA;

            float4 A[4], B[4];             // rolling quads (32 regs)
#pragma unroll
            for (int k = 0; k < 4; ++k)
                B[k] = *(const float4*)(sbase + k * ROWA + PADL + w4);

            int pb = PADL + w4 - 4;        // quad-aligned, >= 0 for all groups
            float* op = out + ((size_t)g * DD * HH + h) * WW + w4 + 2 * kh;

            // one disparity sub-step: F = [LO|HI] flattened, out j uses F[4 + j - T]
#define GWC_STEP(LO, HI, T)                                                     \
            {                                                                   \
                float a0 = 0.f, a1 = 0.f, a2 = 0.f, a3 = 0.f;                   \
                _Pragma("unroll")                                               \
                for (int k = 0; k < 4; ++k) {                                   \
                    const float F[8] = { LO[k].x, LO[k].y, LO[k].z, LO[k].w,    \
                                         HI[k].x, HI[k].y, HI[k].z, HI[k].w };  \
                    a0 += r[k][0] * F[4 + 0 - (T)];                             \
                    a1 += r[k][1] * F[4 + 1 - (T)];                             \
                    a2 += r[k][2] * F[4 + 2 - (T)];                             \
                    a3 += r[k][3] * F[4 + 3 - (T)];                             \
                }                                                               \
                float v0 = kh ? a0 : a2;                                        \
                float v1 = kh ? a1 : a3;                                        \
                float u0 = __shfl_xor_sync(0xffffffffu, v0, 1);                 \
                float u1 = __shfl_xor_sync(0xffffffffu, v1, 1);                 \
                if (active) {                                                   \
                    float2 o;                                                   \
                    if (kh == 0) { o.x = a0 + u0; o.y = a1 + u1; }              \
                    else         { o.x = a2 + u0; o.y = a3 + u1; }              \
                    stwt2(op, o);                                               \
                }                                                               \
                op += HH * WW;                                                  \
            }

#pragma unroll
            for (int dp = 0; dp < DD / 8; ++dp) {
                // group A: lo = A (newly loaded), hi = B
#pragma unroll
                for (int k = 0; k < 4; ++k) A[k] = *(const float4*)(sbase + k * ROWA + pb);
                GWC_STEP(A, B, 0) GWC_STEP(A, B, 1) GWC_STEP(A, B, 2) GWC_STEP(A, B, 3)
                pb -= 4;
                // group B: lo = B (newly loaded), hi = A
#pragma unroll
                for (int k = 0; k < 4; ++k) B[k] = *(const float4*)(sbase + k * ROWA + pb);
                GWC_STEP(B, A, 0) GWC_STEP(B, A, 1) GWC_STEP(B, A, 2) GWC_STEP(B, A, 3)
                pb -= 4;
            }
#undef GWC_STEP
        };

        CP_WAIT(1);            // unit 0 tile resident (groups retire in order)
        __syncthreads();       // pad zeros + unit 0 visible to all
        compute(0);
        CP_WAIT(0);            // unit 1 tile resident (streamed during compute(0))
        __syncthreads();
        compute(1);
    } else {
        // ===== concat block: one (c, d) plane; 240 threads = 60 wq x 4 h-quarters =====
        const int d = wid_ % DD;
        const int c = wid_ / DD;
        if (tid >= 240) return;
        const int wq = tid % 60;
        const int qt = tid / 60;           // h quarter (32 rows)
        const int wb = wq * 4;
        const int h0 = qt * 32;

        float* ob = out + ((((size_t)(NG + c) * DD + d) * HH) + h0) * WW + wb;

        if (c < 12) {
            const bool m0 = (wb + 0 >= d), m1 = (wb + 1 >= d),
                       m2 = (wb + 2 >= d), m3 = (wb + 3 >= d);
            const float* ib = refc + (((size_t)c * HH) + h0) * WW + wb;
#pragma unroll 4
            for (int h = 0; h < 32; ++h) {
                float4 x = *(const float4*)(ib + h * WW);
                float4 v;
                v.x = m0 ? x.x : 0.f;
                v.y = m1 ? x.y : 0.f;
                v.z = m2 ? x.z : 0.f;
                v.w = m3 ? x.w : 0.f;
                stwt4(ob + h * WW, v);
            }
        } else {
            // right-shifted tgt plane via aligned quad pair + uniform select
            const float* base = tgtc + (((size_t)(c - 12) * HH) + h0) * WW;
            const int sh = d & 3;
            if (sh == 0) {
                const int lo = wb - d;                 // quad aligned
                if (lo >= 0) {
                    const float* ib = base + lo;
#pragma unroll 4
                    for (int h = 0; h < 32; ++h)
                        stwt4(ob + h * WW, *(const float4*)(ib + h * WW));
                } else {
                    float4 z = make_float4(0.f, 0.f, 0.f, 0.f);
#pragma unroll 4
                    for (int h = 0; h < 32; ++h)
                        stwt4(ob + h * WW, z);
                }
            } else {
                const int off = 4 - sh;                // 1..3
                const int lo = wb - d - off;           // quad aligned
                const int hi4 = lo + 4;                // <= 236 when >= 0: in bounds
                const bool ldlo = (lo >= 0), ldhi = (hi4 >= 0);
                const float4 z = make_float4(0.f, 0.f, 0.f, 0.f);
#pragma unroll 4
                for (int h = 0; h < 32; ++h) {
                    float4 L = ldlo ? *(const float4*)(base + h * WW + lo)  : z;
                    float4 H = ldhi ? *(const float4*)(base + h * WW + hi4) : z;
                    float4 v;
                    if (off == 1)      { v.x = L.y; v.y = L.z; v.z = L.w; v.w = H.x; }
                    else if (off == 2) { v.x = L.z; v.y = L.w; v.z = H.x; v.w = H.y; }
                    else               { v.x = L.w; v.y = H.x; v.z = H.y; v.w = H.z; }
                    stwt4(ob + h * WW, v);
                }
            }
        }
    }
}

extern "C" void kernel_launch(void* const* d_in, const int* in_sizes, int n_in,
                              void* d_out, int out_size) {
    const float* ref_gwc    = (const float*)d_in[0];
    const float* tgt_gwc    = (const float*)d_in[1];
    const float* ref_concat = (const float*)d_in[2];
    const float* tgt_concat = (const float*)d_in[3];
    float* out = (float*)d_out;

    fused_kernel<<<TOTAL_BLOCKS, TPB>>>(ref_gwc, tgt_gwc, ref_concat, tgt_concat, out);
}

// round 17
// speedup vs baseline: 2.3014x; 1.3414x over previous
#include <cuda_runtime.h>
#include <cstdint>

// Fixed problem shape
#define HH 128
#define WW 240
#define NG 40
#define CPG 8
#define DD 48
#define PADL 48
#define NPOS (WW + PADL)   // 288 positions per smem row
#define ROWA 292           // stride ≡ 4 (mod 8): kh halves hit disjoint bank sets
#define TPB 256

#define SMEM_UNIT (2 * CPG * ROWA)     // floats per unit buffer (16 rows)

#define GWC_BLOCKS (NG * (HH / 4))     // 1280 (each block: 4 h rows = 2 units)
#define CAT_BLOCKS (24 * DD)           // 1152
#define EXTRA_GWC (GWC_BLOCKS - CAT_BLOCKS)   // 128 unpaired gwc blocks, launched FIRST
#define TOTAL_BLOCKS (GWC_BLOCKS + CAT_BLOCKS)  // 2432

__device__ __forceinline__ void stcs4(float* p, float4 v) { __stcs((float4*)p, v); }
__device__ __forceinline__ void stcs2(float* p, float2 v) { __stcs((float2*)p, v); }

__device__ __forceinline__ uint32_t smem_u32(const void* p) {
    return (uint32_t)__cvta_generic_to_shared(p);
}
__device__ __forceinline__ void cpasync16(uint32_t dst, const void* src) {
    asm volatile("cp.async.cg.shared.global [%0], [%1], 16;" :: "r"(dst), "l"(src));
}
#define CP_COMMIT() asm volatile("cp.async.commit_group;")
#define CP_WAIT(N)  asm volatile("cp.async.wait_group %0;" :: "n"(N))

// RF cap: 64K regs/SM -> 1024 threads at 64 regs = 4 blocks of 256.
__global__ __launch_bounds__(TPB, 4)
void fused_kernel(const float* __restrict__ ref, const float* __restrict__ tgt,
                  const float* __restrict__ refc, const float* __restrict__ tgtc,
                  float* __restrict__ out) {
    __shared__ __align__(16) float s[2 * SMEM_UNIT];   // 37376 B (2 unit buffers)

    const int bid = blockIdx.x;
    const int tid = threadIdx.x;

    // ---- schedule: 128 pure-gwc blocks first (longest pole), then alternate gwc/cat ----
    bool is_cat;
    int wid_;
    if (bid < EXTRA_GWC) {
        is_cat = false;
        wid_ = CAT_BLOCKS + bid;            // 1152..1279
    } else {
        const int b = bid - EXTRA_GWC;      // 0..2303
        is_cat = (b & 1);
        wid_ = b >> 1;                      // 0..1151
    }

    if (!is_cat) {
        // ===== gwc block: group g, h rows hb..hb+3, two pipelined units =====
        const int g  = wid_ % NG;
        const int hb = (wid_ / NG) * 4;

        // pad zeros for both buffers (positions < PADL): 2 x 16 rows x 12 quads
        for (int i = tid; i < 2 * 16 * 12; i += TPB) {
            const int b = i / (16 * 12), r2 = (i / 12) & 15, j = i % 12;
            *(float4*)(s + b * SMEM_UNIT + r2 * ROWA + j * 4) =
                make_float4(0.f, 0.f, 0.f, 0.f);
        }
        // issue BOTH units' tile loads up front; unit 1 streams in during unit 0 compute
#pragma unroll
        for (int u = 0; u < 2; ++u) {
            const int h0 = hb + u * 2;
            float* dbase = s + u * SMEM_UNIT;
            for (int i = tid; i < 16 * 60; i += TPB) {
                const int r2 = i / 60, j = i - r2 * 60;
                const int c = r2 & 7, hr = r2 >> 3;
                const float* src = tgt + (((size_t)(g * CPG + c)) * HH + h0 + hr) * WW + j * 4;
                cpasync16(smem_u32(dbase + r2 * ROWA + PADL + j * 4), src);
            }
            CP_COMMIT();
        }

        // per-thread role (same for both units)
        const int sub = tid & 127;
        const int hr  = tid >> 7;          // which h row of the unit (warp-uniform)
        const int kh  = sub & 1;           // 0 -> channels 0..3, 1 -> channels 4..7
        int q = sub >> 1;                  // w-quad id 0..63
        const bool active = (q < 60);
        if (q > 59) q = 59;                // keep warps converged for shfl
        const int w4 = q * 4;

        auto compute = [&](int u) {
            const int h = hb + u * 2 + hr;

            // ref: 4 channels x 4 w, x1/8 folded (16 regs)
            float r[4][4];
#pragma unroll
            for (int k = 0; k < 4; ++k) {
                float4 v = *(const float4*)(ref + (((size_t)(g * CPG + kh * 4 + k)) * HH + h) * WW + w4);
                r[k][0] = v.x * 0.125f; r[k][1] = v.y * 0.125f;
                r[k][2] = v.z * 0.125f; r[k][3] = v.w * 0.125f;
            }

            const float* sbase = s + u * SMEM_UNIT + (hr * 8 + kh * 4) * ROWA;

            float4 A[4], B[4];             // rolling quads (32 regs)
#pragma unroll
            for (int k = 0; k < 4; ++k)
                B[k] = *(const float4*)(sbase + k * ROWA + PADL + w4);

            int pb = PADL + w4 - 4;        // quad-aligned, >= 0 for all groups
            float* op = out + ((size_t)g * DD * HH + h) * WW + w4 + 2 * kh;

            // one disparity sub-step: F = [LO|HI] flattened, out j uses F[4 + j - T]
#define GWC_STEP(LO, HI, T)                                                     \
            {                                                                   \
                float a0 = 0.f, a1 = 0.f, a2 = 0.f, a3 = 0.f;                   \
                _Pragma("unroll")                                               \
                for (int k = 0; k < 4; ++k) {                                   \
                    const float F[8] = { LO[k].x, LO[k].y, LO[k].z, LO[k].w,    \
                                         HI[k].x, HI[k].y, HI[k].z, HI[k].w };  \
                    a0 += r[k][0] * F[4 + 0 - (T)];                             \
                    a1 += r[k][1] * F[4 + 1 - (T)];                             \
                    a2 += r[k][2] * F[4 + 2 - (T)];                             \
                    a3 += r[k][3] * F[4 + 3 - (T)];                             \
                }                                                               \
                float v0 = kh ? a0 : a2;                                        \
                float v1 = kh ? a1 : a3;                                        \
                float u0 = __shfl_xor_sync(0xffffffffu, v0, 1);                 \
                float u1 = __shfl_xor_sync(0xffffffffu, v1, 1);                 \
                if (active) {                                                   \
                    float2 o;                                                   \
                    if (kh == 0) { o.x = a0 + u0; o.y = a1 + u1; }              \
                    else         { o.x = a2 + u0; o.y = a3 + u1; }              \
                    stcs2(op, o);                                               \
                }                                                               \
                op += HH * WW;                                                  \
            }

#pragma unroll
            for (int dp = 0; dp < DD / 8; ++dp) {
                // group A: lo = A (newly loaded), hi = B
#pragma unroll
                for (int k = 0; k < 4; ++k) A[k] = *(const float4*)(sbase + k * ROWA + pb);
                GWC_STEP(A, B, 0) GWC_STEP(A, B, 1) GWC_STEP(A, B, 2) GWC_STEP(A, B, 3)
                pb -= 4;
                // group B: lo = B (newly loaded), hi = A
#pragma unroll
                for (int k = 0; k < 4; ++k) B[k] = *(const float4*)(sbase + k * ROWA + pb);
                GWC_STEP(B, A, 0) GWC_STEP(B, A, 1) GWC_STEP(B, A, 2) GWC_STEP(B, A, 3)
                pb -= 4;
            }
#undef GWC_STEP
        };

        CP_WAIT(1);            // unit 0 tile resident (groups retire in order)
        __syncthreads();       // pad zeros + unit 0 visible to all
        compute(0);
        CP_WAIT(0);            // unit 1 tile resident (streamed during compute(0))
        __syncthreads();
        compute(1);
    } else {
        // ===== concat block: one (c, d) plane; 240 threads = 60 wq x 4 h-quarters =====
        const int d = wid_ % DD;
        const int c = wid_ / DD;
        if (tid >= 240) return;
        const int wq = tid % 60;
        const int qt = tid / 60;           // h quarter (32 rows)
        const int wb = wq * 4;
        const int h0 = qt * 32;

        float* ob = out + ((((size_t)(NG + c) * DD + d) * HH) + h0) * WW + wb;

        if (c < 12) {
            const bool m0 = (wb + 0 >= d), m1 = (wb + 1 >= d),
                       m2 = (wb + 2 >= d), m3 = (wb + 3 >= d);
            const float* ib = refc + (((size_t)c * HH) + h0) * WW + wb;
#pragma unroll 4
            for (int h = 0; h < 32; ++h) {
                float4 x = *(const float4*)(ib + h * WW);
                float4 v;
                v.x = m0 ? x.x : 0.f;
                v.y = m1 ? x.y : 0.f;
                v.z = m2 ? x.z : 0.f;
                v.w = m3 ? x.w : 0.f;
                stcs4(ob + h * WW, v);
            }
        } else {
            // right-shifted tgt plane via aligned quad pair + uniform select
            const float* base = tgtc + (((size_t)(c - 12) * HH) + h0) * WW;
            const int sh = d & 3;
            if (sh == 0) {
                const int lo = wb - d;                 // quad aligned
                if (lo >= 0) {
                    const float* ib = base + lo;
#pragma unroll 4
                    for (int h = 0; h < 32; ++h)
                        stcs4(ob + h * WW, *(const float4*)(ib + h * WW));
                } else {
                    float4 z = make_float4(0.f, 0.f, 0.f, 0.f);
#pragma unroll 4
                    for (int h = 0; h < 32; ++h)
                        stcs4(ob + h * WW, z);
                }
            } else {
                const int off = 4 - sh;                // 1..3
                const int lo = wb - d - off;           // quad aligned
                const int hi4 = lo + 4;                // <= 236 when >= 0: in bounds
                const bool ldlo = (lo >= 0), ldhi = (hi4 >= 0);
                const float4 z = make_float4(0.f, 0.f, 0.f, 0.f);
#pragma unroll 4
                for (int h = 0; h < 32; ++h) {
                    float4 L = ldlo ? *(const float4*)(base + h * WW + lo)  : z;
                    float4 H = ldhi ? *(const float4*)(base + h * WW + hi4) : z;
                    float4 v;
                    if (off == 1)      { v.x = L.y; v.y = L.z; v.z = L.w; v.w = H.x; }
                    else if (off == 2) { v.x = L.z; v.y = L.w; v.z = H.x; v.w = H.y; }
                    else               { v.x = L.w; v.y = H.x; v.z = H.y; v.w = H.z; }
                    stcs4(ob + h * WW, v);
                }
            }
        }
    }
}

extern "C" void kernel_launch(void* const* d_in, const int* in_sizes, int n_in,
                              void* d_out, int out_size) {
    const float* ref_gwc    = (const float*)d_in[0];
    const float* tgt_gwc    = (const float*)d_in[1];
    const float* ref_concat = (const float*)d_in[2];
    const float* tgt_concat = (const float*)d_in[3];
    float* out = (float*)d_out;

    fused_kernel<<<TOTAL_BLOCKS, TPB>>>(ref_gwc, tgt_gwc, ref_concat, tgt_concat, out);
}